// round 5
// baseline (speedup 1.0000x reference)
#include <cuda_runtime.h>
#include <cstdint>

#define B 2048
#define N 65536
#define F 128
#define TOPK 3
#define NLAB 10
#define SPLITS 9
#define CHUNKS (N / 128)  // 512 chunks of 128 candidates

// ---------------- device scratch (no allocations allowed) ----------------
__device__ float g_xfT[F * B];        // (x * features) transposed: [f][b], 1 MB
__device__ float g_trainT[F * N];     // train transposed: [f][n], 32 MB
__device__ float g_left[B];           // sum(x^2) per query
__device__ float g_right[N];          // sum((feat*train)^2) per candidate
__device__ float g_pval[B * SPLITS * TOPK];
__device__ int   g_pidx[B * SPLITS * TOPK];

// ---------------- helpers ----------------
__device__ __forceinline__ void cp_async16(uint32_t saddr, const void* gaddr) {
    asm volatile("cp.async.cg.shared.global [%0], [%1], 16;\n" :: "r"(saddr), "l"(gaddr));
}

__device__ __forceinline__ bool better(float v, int i, float V, int I) {
    // jax.lax.top_k order: larger value first; ties -> lower index first
    return (v > V) || (v == V && i < I);
}

__device__ __forceinline__ void insert_cmp(float* bv, int* bi, float v, int i) {
    if (!better(v, i, bv[2], bi[2])) return;
    if (better(v, i, bv[0], bi[0])) {
        bv[2] = bv[1]; bi[2] = bi[1];
        bv[1] = bv[0]; bi[1] = bi[0];
        bv[0] = v;     bi[0] = i;
    } else if (better(v, i, bv[1], bi[1])) {
        bv[2] = bv[1]; bi[2] = bi[1];
        bv[1] = v;     bi[1] = i;
    } else {
        bv[2] = v;     bi[2] = i;
    }
}

// ---------------- prep: left[b], xfT ----------------
__global__ void prep_x_kernel(const float* __restrict__ x, const float* __restrict__ feats) {
    int warp = (blockIdx.x * blockDim.x + threadIdx.x) >> 5;
    int lane = threadIdx.x & 31;
    if (warp >= B) return;
    float4 xv = *(const float4*)&x[warp * F + lane * 4];
    float4 fv = *(const float4*)&feats[lane * 4];
    float s = xv.x * xv.x + xv.y * xv.y + xv.z * xv.z + xv.w * xv.w;
    #pragma unroll
    for (int o = 16; o; o >>= 1) s += __shfl_xor_sync(0xffffffffu, s, o);
    if (lane == 0) g_left[warp] = s;
    int f0 = lane * 4;
    g_xfT[(f0 + 0) * B + warp] = xv.x * fv.x;
    g_xfT[(f0 + 1) * B + warp] = xv.y * fv.y;
    g_xfT[(f0 + 2) * B + warp] = xv.z * fv.z;
    g_xfT[(f0 + 3) * B + warp] = xv.w * fv.w;
}

// ---------------- prep: right[n] ----------------
__global__ void prep_right_kernel(const float* __restrict__ train, const float* __restrict__ feats) {
    int warp = (blockIdx.x * blockDim.x + threadIdx.x) >> 5;
    int lane = threadIdx.x & 31;
    if (warp >= N) return;
    float4 tv = *(const float4*)&train[warp * F + lane * 4];
    float4 fv = *(const float4*)&feats[lane * 4];
    float wx = tv.x * fv.x, wy = tv.y * fv.y, wz = tv.z * fv.z, ww = tv.w * fv.w;
    float s = wx * wx + wy * wy + wz * wz + ww * ww;
    #pragma unroll
    for (int o = 16; o; o >>= 1) s += __shfl_xor_sync(0xffffffffu, s, o);
    if (lane == 0) g_right[warp] = s;
}

// ---------------- prep: trainT = (feats * train) transposed ----------------
__global__ void transpose_kernel(const float* __restrict__ train, const float* __restrict__ feats) {
    __shared__ float tile[32][33];
    int n0 = blockIdx.x * 32, f0 = blockIdx.y * 32;
    int tx = threadIdx.x, ty = threadIdx.y;  // block (32, 8)
    float fscale = feats[f0 + tx];
    #pragma unroll
    for (int r = 0; r < 32; r += 8)
        tile[ty + r][tx] = train[(n0 + ty + r) * F + f0 + tx] * fscale;
    __syncthreads();
    #pragma unroll
    for (int r = 0; r < 32; r += 8)
        g_trainT[(f0 + ty + r) * N + n0 + tx] = tile[tx][ty + r];
}

// ---------------- main fused GEMM + top-3 ----------------
// grid (B/128, SPLITS) = 144 blocks (1 wave / 148 SMs), 256 threads, 192 KB smem
// Xs [k][q] 128x128 (64 KB) resident; Ws [2][k][c] double-buffered (128 KB)
extern "C" __global__ void __launch_bounds__(256, 1) knn_main_kernel() {
    extern __shared__ float smem[];
    float* Xs = smem;
    float* Ws = smem + 128 * 128;

    const int tid = threadIdx.x;
    const int tx = tid & 15;    // candidate group (8 cands)
    const int ty = tid >> 4;    // query group (8 queries)
    const int qbase = blockIdx.x * 128;
    const int c0 = (blockIdx.y * CHUNKS) / SPLITS;
    const int c1 = ((blockIdx.y + 1) * CHUNKS) / SPLITS;

    uint32_t sX = (uint32_t)__cvta_generic_to_shared(Xs);
    uint32_t sW = (uint32_t)__cvta_generic_to_shared(Ws);

    // Fill X tile (128 f-rows x 128 queries) + first W tile.
    // Tile = 16384 floats = 4096 float4s; 256 threads -> 16 float4s each.
    // Each row holds 128 floats = 32 float4s: row = idx>>5, col = (idx&31)*4.
    #pragma unroll
    for (int i = 0; i < 16; i++) {
        int idx = tid + i * 256;
        int row = idx >> 5, col = (idx & 31) * 4;
        cp_async16(sX + (row * 128 + col) * 4, &g_xfT[row * B + qbase + col]);
    }
    #pragma unroll
    for (int i = 0; i < 16; i++) {
        int idx = tid + i * 256;
        int row = idx >> 5, col = (idx & 31) * 4;
        cp_async16(sW + (row * 128 + col) * 4, &g_trainT[row * N + c0 * 128 + col]);
    }
    asm volatile("cp.async.commit_group;\n");

    float lq[8];
    #pragma unroll
    for (int i = 0; i < 8; i++) lq[i] = g_left[qbase + ty * 8 + i];

    float tv[8][3];
    int   ti[8][3];
    #pragma unroll
    for (int i = 0; i < 8; i++)
        #pragma unroll
        for (int k = 0; k < 3; k++) { tv[i][k] = -3.4e38f; ti[i][k] = 0x7fffffff; }

    int cur = 0;
    for (int c = c0; c < c1; ++c) {
        // prefetch next W tile into the other buffer
        if (c + 1 < c1) {
            uint32_t sWn = sW + (cur ^ 1) * 128 * 128 * 4;
            #pragma unroll
            for (int i = 0; i < 16; i++) {
                int idx = tid + i * 256;
                int row = idx >> 5, col = (idx & 31) * 4;
                cp_async16(sWn + (row * 128 + col) * 4,
                           &g_trainT[row * N + (c + 1) * 128 + col]);
            }
            asm volatile("cp.async.commit_group;\n");
            asm volatile("cp.async.wait_group 1;\n");
        } else {
            asm volatile("cp.async.wait_group 0;\n");
        }
        __syncthreads();

        const float* Wc = Ws + cur * 128 * 128;
        unsigned long long acc[32];
        #pragma unroll
        for (int i = 0; i < 32; i++) acc[i] = 0ull;

        #pragma unroll 8
        for (int kk = 0; kk < 128; ++kk) {
            float4 xa = *(const float4*)&Xs[kk * 128 + ty * 8];
            float4 xb = *(const float4*)&Xs[kk * 128 + ty * 8 + 4];
            ulonglong2 w01 = *(const ulonglong2*)&Wc[kk * 128 + tx * 8];
            ulonglong2 w23 = *(const ulonglong2*)&Wc[kk * 128 + tx * 8 + 4];
            float xs[8] = {xa.x, xa.y, xa.z, xa.w, xb.x, xb.y, xb.z, xb.w};
            #pragma unroll
            for (int i = 0; i < 8; i++) {
                unsigned long long a2;
                asm("mov.b64 %0, {%1, %1};" : "=l"(a2) : "r"(__float_as_uint(xs[i])));
                asm("fma.rn.f32x2 %0, %1, %2, %0;" : "+l"(acc[i * 4 + 0]) : "l"(a2), "l"(w01.x));
                asm("fma.rn.f32x2 %0, %1, %2, %0;" : "+l"(acc[i * 4 + 1]) : "l"(a2), "l"(w01.y));
                asm("fma.rn.f32x2 %0, %1, %2, %0;" : "+l"(acc[i * 4 + 2]) : "l"(a2), "l"(w23.x));
                asm("fma.rn.f32x2 %0, %1, %2, %0;" : "+l"(acc[i * 4 + 3]) : "l"(a2), "l"(w23.y));
            }
        }

        // epilogue: distance + per-thread top-3
        // IEEE sqrt (__fsqrt_rn) to bit-match XLA's pow(x, 0.5) -> sqrt.rn lowering:
        // removes the dominant controllable ordering-noise term (~3e-6 abs from
        // sqrt.approx) against near-tied 3rd/4th neighbors.
        const int cb = c * 128 + tx * 8;
        float rr[8];
        #pragma unroll
        for (int j = 0; j < 8; j++) rr[j] = g_right[cb + j];
        #pragma unroll
        for (int i = 0; i < 8; i++) {
            float L = lq[i];
            #pragma unroll
            for (int j = 0; j < 4; j++) {
                unsigned int u0, u1;
                asm("mov.b64 {%0, %1}, %2;" : "=r"(u0), "=r"(u1) : "l"(acc[i * 4 + j]));
                float d0 = __uint_as_float(u0);
                float d1 = __uint_as_float(u1);
                float s0 = __fsqrt_rn(L + rr[j * 2]);
                float s1 = __fsqrt_rn(L + rr[j * 2 + 1]);
                float v0c = 2.0f * d0 - s0;   // = -distance
                float v1c = 2.0f * d1 - s1;
                int n0 = cb + j * 2;
                insert_cmp(tv[i], ti[i], v0c, n0);
                insert_cmp(tv[i], ti[i], v1c, n0 + 1);
            }
        }
        __syncthreads();   // all reads of buffer `cur` done before it is refilled
        cur ^= 1;
    }

    // block-level merge across the 16 candidate-group threads (reuse Xs smem)
    float* sV = smem;                       // 128 * 48 floats = 24 KB
    int*   sI = (int*)(smem + 128 * 48);    // 24 KB
    #pragma unroll
    for (int i = 0; i < 8; i++) {
        int q = ty * 8 + i;
        #pragma unroll
        for (int k = 0; k < 3; k++) {
            sV[(q * 16 + tx) * 3 + k] = tv[i][k];
            sI[(q * 16 + tx) * 3 + k] = ti[i][k];
        }
    }
    __syncthreads();
    if (tid < 128) {
        float bv[3] = {-3.4e38f, -3.4e38f, -3.4e38f};
        int   bi[3] = {0x7fffffff, 0x7fffffff, 0x7fffffff};
        for (int e = 0; e < 48; e++)
            insert_cmp(bv, bi, sV[tid * 48 + e], sI[tid * 48 + e]);
        int b = qbase + tid;
        int base = (b * SPLITS + blockIdx.y) * 3;
        #pragma unroll
        for (int k = 0; k < 3; k++) { g_pval[base + k] = bv[k]; g_pidx[base + k] = bi[k]; }
    }
}

// ---------------- finalize: merge splits, labels, one-hot ----------------
__global__ void finalize_kernel(const int* __restrict__ labels, float* __restrict__ out) {
    int b = blockIdx.x * blockDim.x + threadIdx.x;
    if (b >= B) return;
    float bv[3] = {-3.4e38f, -3.4e38f, -3.4e38f};
    int   bi[3] = {0x7fffffff, 0x7fffffff, 0x7fffffff};
    #pragma unroll
    for (int e = 0; e < SPLITS * 3; e++)
        insert_cmp(bv, bi, g_pval[b * SPLITS * 3 + e], g_pidx[b * SPLITS * 3 + e]);

    int l0 = labels[bi[0]], l1 = labels[bi[1]], l2 = labels[bi[2]];
    int lab = (l0 + l1 + l2) / TOPK;  // labels >= 0 -> trunc == floor

    // output layout (float32, reference tuple order):
    // [0, B*10)            one_hot
    // [B*10, B*13)         values
    // [B*13, B*16)         indices
    // [B*16, B*19)         labels
    #pragma unroll
    for (int c = 0; c < NLAB; c++) out[b * NLAB + c] = (c == lab) ? 1.0f : 0.0f;
    float* ov = out + B * NLAB;
    float* oi = out + B * (NLAB + 3);
    float* ol = out + B * (NLAB + 6);
    ov[b * 3 + 0] = bv[0]; ov[b * 3 + 1] = bv[1]; ov[b * 3 + 2] = bv[2];
    oi[b * 3 + 0] = (float)bi[0]; oi[b * 3 + 1] = (float)bi[1]; oi[b * 3 + 2] = (float)bi[2];
    ol[b * 3 + 0] = (float)l0; ol[b * 3 + 1] = (float)l1; ol[b * 3 + 2] = (float)l2;
}

// ---------------- launch ----------------
extern "C" void kernel_launch(void* const* d_in, const int* in_sizes, int n_in,
                              void* d_out, int out_size) {
    const float* x      = (const float*)d_in[0];
    const float* train  = (const float*)d_in[1];
    const int*   labels = (const int*)d_in[2];
    const float* feats  = (const float*)d_in[3];
    float* out = (float*)d_out;

    cudaFuncSetAttribute(knn_main_kernel, cudaFuncAttributeMaxDynamicSharedMemorySize, 196608);

    prep_x_kernel<<<B / 8, 256>>>(x, feats);
    prep_right_kernel<<<N / 8, 256>>>(train, feats);
    transpose_kernel<<<dim3(N / 32, F / 32), dim3(32, 8)>>>(train, feats);
    knn_main_kernel<<<dim3(B / 128, SPLITS), 256, 196608>>>();
    finalize_kernel<<<(B + 255) / 256, 256>>>(labels, out);
}

// round 9
// speedup vs baseline: 1.1798x; 1.1798x over previous
#include <cuda_runtime.h>
#include <cstdint>

#define B 2048
#define N 65536
#define F 128
#define TOPK 3
#define NLAB 10
#define SPLITS 9
#define CHUNKS (N / 128)  // 512 chunks of 128 candidates

// ---------------- device scratch (no allocations allowed) ----------------
__device__ float g_xfT[F * B];        // (x * features) transposed: [f][b], 1 MB
__device__ float g_trainT[F * N];     // train transposed: [f][n], 32 MB
__device__ float g_left[B];           // sum(x^2) per query
__device__ float g_right[N];          // sum((feat*train)^2) per candidate
__device__ float g_pval[B * SPLITS * TOPK];
__device__ int   g_pidx[B * SPLITS * TOPK];

// ---------------- helpers ----------------
__device__ __forceinline__ void cp_async16(uint32_t saddr, const void* gaddr) {
    asm volatile("cp.async.cg.shared.global [%0], [%1], 16;\n" :: "r"(saddr), "l"(gaddr));
}

__device__ __forceinline__ bool better(float v, int i, float V, int I) {
    // jax.lax.top_k order: larger value first; ties -> lower index first
    return (v > V) || (v == V && i < I);
}

__device__ __forceinline__ void insert_cmp(float* bv, int* bi, float v, int i) {
    if (!better(v, i, bv[2], bi[2])) return;
    if (better(v, i, bv[0], bi[0])) {
        bv[2] = bv[1]; bi[2] = bi[1];
        bv[1] = bv[0]; bi[1] = bi[0];
        bv[0] = v;     bi[0] = i;
    } else if (better(v, i, bv[1], bi[1])) {
        bv[2] = bv[1]; bi[2] = bi[1];
        bv[1] = v;     bi[1] = i;
    } else {
        bv[2] = v;     bi[2] = i;
    }
}

// ---------------- prep: left[b], xfT ----------------
__global__ void prep_x_kernel(const float* __restrict__ x, const float* __restrict__ feats) {
    int warp = (blockIdx.x * blockDim.x + threadIdx.x) >> 5;
    int lane = threadIdx.x & 31;
    if (warp >= B) return;
    float4 xv = *(const float4*)&x[warp * F + lane * 4];
    float4 fv = *(const float4*)&feats[lane * 4];
    float s = xv.x * xv.x + xv.y * xv.y + xv.z * xv.z + xv.w * xv.w;
    #pragma unroll
    for (int o = 16; o; o >>= 1) s += __shfl_xor_sync(0xffffffffu, s, o);
    if (lane == 0) g_left[warp] = s;
    int f0 = lane * 4;
    g_xfT[(f0 + 0) * B + warp] = xv.x * fv.x;
    g_xfT[(f0 + 1) * B + warp] = xv.y * fv.y;
    g_xfT[(f0 + 2) * B + warp] = xv.z * fv.z;
    g_xfT[(f0 + 3) * B + warp] = xv.w * fv.w;
}

// ---------------- prep: right[n] ----------------
__global__ void prep_right_kernel(const float* __restrict__ train, const float* __restrict__ feats) {
    int warp = (blockIdx.x * blockDim.x + threadIdx.x) >> 5;
    int lane = threadIdx.x & 31;
    if (warp >= N) return;
    float4 tv = *(const float4*)&train[warp * F + lane * 4];
    float4 fv = *(const float4*)&feats[lane * 4];
    float wx = tv.x * fv.x, wy = tv.y * fv.y, wz = tv.z * fv.z, ww = tv.w * fv.w;
    float s = wx * wx + wy * wy + wz * wz + ww * ww;
    #pragma unroll
    for (int o = 16; o; o >>= 1) s += __shfl_xor_sync(0xffffffffu, s, o);
    if (lane == 0) g_right[warp] = s;
}

// ---------------- prep: trainT = (feats * train) transposed ----------------
__global__ void transpose_kernel(const float* __restrict__ train, const float* __restrict__ feats) {
    __shared__ float tile[32][33];
    int n0 = blockIdx.x * 32, f0 = blockIdx.y * 32;
    int tx = threadIdx.x, ty = threadIdx.y;  // block (32, 8)
    float fscale = feats[f0 + tx];
    #pragma unroll
    for (int r = 0; r < 32; r += 8)
        tile[ty + r][tx] = train[(n0 + ty + r) * F + f0 + tx] * fscale;
    __syncthreads();
    #pragma unroll
    for (int r = 0; r < 32; r += 8)
        g_trainT[(f0 + ty + r) * N + n0 + tx] = tile[tx][ty + r];
}

// ---------------- main fused GEMM + top-3 ----------------
// grid (B/128, SPLITS) = 144 blocks, 512 threads (16 warps -> 4/SMSP), 192 KB smem
// Xs [k][q] 128x128 (64 KB); Ws [2][k][c] double-buffered (128 KB)
// Per-thread: 8 queries x 4 candidates. f32x2 lanes = QUERY PAIRS (natural X
// loads, no packing); the 4 W scalars are lane-duplicated (4 dups/kk).
// kk unroll kept at 4 to stay under the 128-reg cap (512 thr) without spills.
extern "C" __global__ void __launch_bounds__(512, 1) knn_main_kernel() {
    extern __shared__ float smem[];
    float* Xs = smem;
    float* Ws = smem + 128 * 128;

    const int tid = threadIdx.x;
    const int tx = tid & 31;    // candidate group (4 cands)  -> warp lanes span tx 0..31
    const int ty = tid >> 5;    // query group (8 queries)    -> whole warp shares ty (X broadcast)
    const int qbase = blockIdx.x * 128;
    const int c0 = (blockIdx.y * CHUNKS) / SPLITS;
    const int c1 = ((blockIdx.y + 1) * CHUNKS) / SPLITS;

    uint32_t sX = (uint32_t)__cvta_generic_to_shared(Xs);
    uint32_t sW = (uint32_t)__cvta_generic_to_shared(Ws);

    // Fill X tile + first W tile: 4096 float4s each, 512 threads -> 8 each.
    // Row = 128 floats = 32 float4s: row = idx>>5, col = (idx&31)*4.
    #pragma unroll
    for (int i = 0; i < 8; i++) {
        int idx = tid + i * 512;
        int row = idx >> 5, col = (idx & 31) * 4;
        cp_async16(sX + (row * 128 + col) * 4, &g_xfT[row * B + qbase + col]);
    }
    #pragma unroll
    for (int i = 0; i < 8; i++) {
        int idx = tid + i * 512;
        int row = idx >> 5, col = (idx & 31) * 4;
        cp_async16(sW + (row * 128 + col) * 4, &g_trainT[row * N + c0 * 128 + col]);
    }
    asm volatile("cp.async.commit_group;\n");

    float lq[8];
    #pragma unroll
    for (int i = 0; i < 8; i++) lq[i] = g_left[qbase + ty * 8 + i];

    float tv[8][3];
    int   ti[8][3];
    #pragma unroll
    for (int i = 0; i < 8; i++)
        #pragma unroll
        for (int k = 0; k < 3; k++) { tv[i][k] = -3.4e38f; ti[i][k] = 0x7fffffff; }

    int cur = 0;
    for (int c = c0; c < c1; ++c) {
        // prefetch next W tile into the other buffer
        if (c + 1 < c1) {
            uint32_t sWn = sW + (cur ^ 1) * 128 * 128 * 4;
            #pragma unroll
            for (int i = 0; i < 8; i++) {
                int idx = tid + i * 512;
                int row = idx >> 5, col = (idx & 31) * 4;
                cp_async16(sWn + (row * 128 + col) * 4,
                           &g_trainT[row * N + (c + 1) * 128 + col]);
            }
            asm volatile("cp.async.commit_group;\n");
            asm volatile("cp.async.wait_group 1;\n");
        } else {
            asm volatile("cp.async.wait_group 0;\n");
        }
        __syncthreads();

        const float* Wc = Ws + cur * 128 * 128;
        // acc[qp*4 + c]: lanes = (query 2qp, query 2qp+1), c = candidate 0..3
        unsigned long long acc[16];
        #pragma unroll
        for (int i = 0; i < 16; i++) acc[i] = 0ull;

        #pragma unroll 4
        for (int kk = 0; kk < 128; ++kk) {
            // natural query-pair loads (broadcast across warp: all lanes same ty)
            ulonglong2 xq01 = *(const ulonglong2*)&Xs[kk * 128 + ty * 8];
            ulonglong2 xq23 = *(const ulonglong2*)&Xs[kk * 128 + ty * 8 + 4];
            // 4 candidate scalars (lanes span 512B -> conflict-free)
            float4 w = *(const float4*)&Wc[kk * 128 + tx * 4];
            unsigned long long xq[4] = {xq01.x, xq01.y, xq23.x, xq23.y};
            float ws[4] = {w.x, w.y, w.z, w.w};
            unsigned long long wd[4];
            #pragma unroll
            for (int j = 0; j < 4; j++)
                asm("mov.b64 %0, {%1, %1};" : "=l"(wd[j]) : "r"(__float_as_uint(ws[j])));
            #pragma unroll
            for (int qp = 0; qp < 4; qp++) {
                asm("fma.rn.f32x2 %0, %1, %2, %0;" : "+l"(acc[qp * 4 + 0]) : "l"(xq[qp]), "l"(wd[0]));
                asm("fma.rn.f32x2 %0, %1, %2, %0;" : "+l"(acc[qp * 4 + 1]) : "l"(xq[qp]), "l"(wd[1]));
                asm("fma.rn.f32x2 %0, %1, %2, %0;" : "+l"(acc[qp * 4 + 2]) : "l"(xq[qp]), "l"(wd[2]));
                asm("fma.rn.f32x2 %0, %1, %2, %0;" : "+l"(acc[qp * 4 + 3]) : "l"(xq[qp]), "l"(wd[3]));
            }
        }

        // epilogue: distance + per-thread top-3
        // IEEE sqrt to bit-match XLA's pow(x,0.5) -> sqrt.rn (rel_err 1.4e-8 proven)
        const int cb = c * 128 + tx * 4;
        float rr[4];
        #pragma unroll
        for (int j = 0; j < 4; j++) rr[j] = g_right[cb + j];
        #pragma unroll
        for (int qp = 0; qp < 4; qp++) {
            float L0 = lq[qp * 2 + 0];
            float L1 = lq[qp * 2 + 1];
            #pragma unroll
            for (int j = 0; j < 4; j++) {
                unsigned int u0, u1;
                asm("mov.b64 {%0, %1}, %2;" : "=r"(u0), "=r"(u1) : "l"(acc[qp * 4 + j]));
                float d0 = __uint_as_float(u0);   // query 2qp
                float d1 = __uint_as_float(u1);   // query 2qp+1
                float s0 = __fsqrt_rn(L0 + rr[j]);
                float s1 = __fsqrt_rn(L1 + rr[j]);
                float v0c = 2.0f * d0 - s0;       // = -distance
                float v1c = 2.0f * d1 - s1;
                int n = cb + j;
                insert_cmp(tv[qp * 2 + 0], ti[qp * 2 + 0], v0c, n);
                insert_cmp(tv[qp * 2 + 1], ti[qp * 2 + 1], v1c, n);
            }
        }
        __syncthreads();   // all reads of buffer `cur` done before it is refilled
        cur ^= 1;
    }

    // block-level merge across the 32 candidate-group threads (reuse smem)
    float* sV = smem;                        // 128 q * 32 tx * 3 = 12288 floats (48 KB)
    int*   sI = (int*)(smem + 128 * 96);     // 48 KB
    #pragma unroll
    for (int i = 0; i < 8; i++) {
        int q = ty * 8 + i;
        #pragma unroll
        for (int k = 0; k < 3; k++) {
            sV[(q * 32 + tx) * 3 + k] = tv[i][k];
            sI[(q * 32 + tx) * 3 + k] = ti[i][k];
        }
    }
    __syncthreads();
    if (tid < 128) {
        float bv[3] = {-3.4e38f, -3.4e38f, -3.4e38f};
        int   bi[3] = {0x7fffffff, 0x7fffffff, 0x7fffffff};
        for (int e = 0; e < 96; e++)
            insert_cmp(bv, bi, sV[tid * 96 + e], sI[tid * 96 + e]);
        int b = qbase + tid;
        int base = (b * SPLITS + blockIdx.y) * 3;
        #pragma unroll
        for (int k = 0; k < 3; k++) { g_pval[base + k] = bv[k]; g_pidx[base + k] = bi[k]; }
    }
}

// ---------------- finalize: merge splits, labels, one-hot ----------------
__global__ void finalize_kernel(const int* __restrict__ labels, float* __restrict__ out) {
    int b = blockIdx.x * blockDim.x + threadIdx.x;
    if (b >= B) return;
    float bv[3] = {-3.4e38f, -3.4e38f, -3.4e38f};
    int   bi[3] = {0x7fffffff, 0x7fffffff, 0x7fffffff};
    #pragma unroll
    for (int e = 0; e < SPLITS * 3; e++)
        insert_cmp(bv, bi, g_pval[b * SPLITS * 3 + e], g_pidx[b * SPLITS * 3 + e]);

    int l0 = labels[bi[0]], l1 = labels[bi[1]], l2 = labels[bi[2]];
    int lab = (l0 + l1 + l2) / TOPK;  // labels >= 0 -> trunc == floor

    // output layout (float32, reference tuple order):
    // [0, B*10)            one_hot
    // [B*10, B*13)         values
    // [B*13, B*16)         indices
    // [B*16, B*19)         labels
    #pragma unroll
    for (int c = 0; c < NLAB; c++) out[b * NLAB + c] = (c == lab) ? 1.0f : 0.0f;
    float* ov = out + B * NLAB;
    float* oi = out + B * (NLAB + 3);
    float* ol = out + B * (NLAB + 6);
    ov[b * 3 + 0] = bv[0]; ov[b * 3 + 1] = bv[1]; ov[b * 3 + 2] = bv[2];
    oi[b * 3 + 0] = (float)bi[0]; oi[b * 3 + 1] = (float)bi[1]; oi[b * 3 + 2] = (float)bi[2];
    ol[b * 3 + 0] = (float)l0; ol[b * 3 + 1] = (float)l1; ol[b * 3 + 2] = (float)l2;
}

// ---------------- launch ----------------
extern "C" void kernel_launch(void* const* d_in, const int* in_sizes, int n_in,
                              void* d_out, int out_size) {
    const float* x      = (const float*)d_in[0];
    const float* train  = (const float*)d_in[1];
    const int*   labels = (const int*)d_in[2];
    const float* feats  = (const float*)d_in[3];
    float* out = (float*)d_out;

    cudaFuncSetAttribute(knn_main_kernel, cudaFuncAttributeMaxDynamicSharedMemorySize, 196608);

    prep_x_kernel<<<B / 8, 256>>>(x, feats);
    prep_right_kernel<<<N / 8, 256>>>(train, feats);
    transpose_kernel<<<dim3(N / 32, F / 32), dim3(32, 8)>>>(train, feats);
    knn_main_kernel<<<dim3(B / 128, SPLITS), 512, 196608>>>();
    finalize_kernel<<<(B + 255) / 256, 256>>>(labels, out);
}